// round 13
// baseline (speedup 1.0000x reference)
#include <cuda_runtime.h>
#include <cuda_fp16.h>
#include <math.h>
#include <stdint.h>

#define B_  4
#define C_  128
#define N_  4096
#define NG  8

// ---------------- scratch (device globals; no allocs) ----------------------
__device__ float   g_part[B_ * NG * C_];
__device__ float   g_mean[B_ * C_];
__device__ __half  g_X[(size_t)B_ * N_ * C_];     // normalized fx, fp16 [b][n][c]
__device__ __half  g_Y[(size_t)B_ * N_ * C_];     // normalized fy, fp16 [b][n][c]
__device__ float   g_A[B_ * N_];                  // per-row 1/sum
// S in fragment-native layout: [cta][step][frag(16)][tid(256)] as uint4 (fp16x8)
__device__ uint4   g_Sf[(size_t)128 * 16 * 16 * 256];   // 128 MB

// ---------------- warp MMA helpers (sm_80 PTX: works on compute_103) -------
__device__ __forceinline__ uint32_t smem_to_u32(const void* p) {
    uint32_t a;
    asm("{ .reg .u64 t; cvta.to.shared.u64 t, %1; cvt.u32.u64 %0, t; }"
        : "=r"(a) : "l"(p));
    return a;
}
__device__ __forceinline__ void ldsm4(uint32_t r[4], uint32_t addr) {
    asm volatile("ldmatrix.sync.aligned.m8n8.x4.shared.b16 {%0,%1,%2,%3}, [%4];"
                 : "=r"(r[0]), "=r"(r[1]), "=r"(r[2]), "=r"(r[3]) : "r"(addr));
}
__device__ __forceinline__ void mma16816(float c[4], const uint32_t a[4],
                                         const uint32_t b[2]) {
    asm volatile("mma.sync.aligned.m16n8k16.row.col.f32.f16.f16.f32 "
                 "{%0,%1,%2,%3}, {%4,%5,%6,%7}, {%8,%9}, {%0,%1,%2,%3};"
                 : "+f"(c[0]), "+f"(c[1]), "+f"(c[2]), "+f"(c[3])
                 : "r"(a[0]), "r"(a[1]), "r"(a[2]), "r"(a[3]),
                   "r"(b[0]), "r"(b[1]));
}

// ---------------- kernel 1a/1b: spatial mean of feature_y ------------------
__global__ void k_mean_part(const float* __restrict__ fy) {
    int b = blockIdx.y, g = blockIdx.x, c = threadIdx.x;
    const float* p = fy + ((size_t)b * N_ + (size_t)g * (N_ / NG)) * C_ + c;
    float s = 0.f;
    for (int n = 0; n < N_ / NG; ++n) s += p[(size_t)n * C_];
    g_part[(b * NG + g) * C_ + c] = s;
}
__global__ void k_mean_final() {
    int b = blockIdx.x, c = threadIdx.x;
    float s = 0.f;
    #pragma unroll
    for (int g = 0; g < NG; ++g) s += g_part[(b * NG + g) * C_ + c];
    g_mean[b * C_ + c] = s * (1.0f / N_);
}

// ---------------- kernel 2: center + L2-normalize -> fp16 ------------------
__global__ __launch_bounds__(256) void k_normalize(const float* __restrict__ fx,
                                                   const float* __restrict__ fy) {
    int w    = blockIdx.x * 8 + (threadIdx.x >> 5);
    int lane = threadIdx.x & 31;
    int b = w / N_, n = w % N_;
    size_t base = ((size_t)b * N_ + n) * C_ + lane * 4;
    float4 xv = *(const float4*)(fx + base);
    float4 yv = *(const float4*)(fy + base);
    float4 mv = *(const float4*)(g_mean + b * C_ + lane * 4);
    float cx[4] = {xv.x - mv.x, xv.y - mv.y, xv.z - mv.z, xv.w - mv.w};
    float cy[4] = {yv.x - mv.x, yv.y - mv.y, yv.z - mv.z, yv.w - mv.w};
    float ssx = cx[0]*cx[0] + cx[1]*cx[1] + cx[2]*cx[2] + cx[3]*cx[3];
    float ssy = cy[0]*cy[0] + cy[1]*cy[1] + cy[2]*cy[2] + cy[3]*cy[3];
    #pragma unroll
    for (int o = 16; o; o >>= 1) {
        ssx += __shfl_xor_sync(0xffffffffu, ssx, o);
        ssy += __shfl_xor_sync(0xffffffffu, ssy, o);
    }
    float sx = 1.0f / (sqrtf(ssx) + 1e-10f);
    float sy = 1.0f / (sqrtf(ssy) + 1e-10f);
    __half2 hx0 = __floats2half2_rn(cx[0]*sx, cx[1]*sx);
    __half2 hx1 = __floats2half2_rn(cx[2]*sx, cx[3]*sx);
    __half2 hy0 = __floats2half2_rn(cy[0]*sy, cy[1]*sy);
    __half2 hy1 = __floats2half2_rn(cy[2]*sy, cy[3]*sy);
    *(uint2*)(g_X + base) = make_uint2(*(uint32_t*)&hx0, *(uint32_t*)&hx1);
    *(uint2*)(g_Y + base) = make_uint2(*(uint32_t*)&hy0, *(uint32_t*)&hy1);
}

// ---------------- kernel 3: fused strip GEMM + row softmax -----------------
// CTA = 128 n-rows x all 4096 m. 8 warps (2n x 4m), warp tile 64x64,
// step tile 128x256, 16 m-steps. Pass 1: GEMM + row max + store S (fp16,
// fragment-native coalesced layout). Pass 2: stream S back + exp-sum.
#define SP      272u                  // padded smem row stride (136 halves)
#define A_BYTES (128u * SP)           // 34816
#define SM_B    A_BYTES
#define BUF_B   (256u * SP)           // 69632
#define SM_RED  (SM_B + 2u * BUF_B)   // 174080
#define SM_FUS  (SM_RED + 5120u)

__device__ __forceinline__ void issue_B(int b, int ms, int tid, uint32_t sb) {
    const char* src = (const char*)(g_Y + ((size_t)b * N_ + ms * 256) * C_);
    uint32_t dst = sb + SM_B + (uint32_t)(ms & 1) * BUF_B;
    #pragma unroll
    for (int k = 0; k < 16; ++k) {
        int cidx = tid + k * 256;
        int row = cidx >> 4, c16 = cidx & 15;
        uint32_t d = dst + (uint32_t)row * SP + (uint32_t)c16 * 16u;
        const char* s = src + (size_t)row * 256 + c16 * 16;
        asm volatile("cp.async.cg.shared.global [%0], [%1], 16;"
                     :: "r"(d), "l"(s) : "memory");
    }
    asm volatile("cp.async.commit_group;" ::: "memory");
}

__device__ __forceinline__ void compute_step(float acc[4][8][4],
                                             uint32_t aaddr, uint32_t baddr) {
    #pragma unroll
    for (int i = 0; i < 4; ++i)
        #pragma unroll
        for (int j = 0; j < 8; ++j)
            #pragma unroll
            for (int k = 0; k < 4; ++k) acc[i][j][k] = 0.f;
    #pragma unroll
    for (int kc = 0; kc < 8; ++kc) {
        uint32_t koff = (uint32_t)kc * 32u;
        uint32_t afr[4][4];
        #pragma unroll
        for (int i = 0; i < 4; ++i)
            ldsm4(afr[i], aaddr + (uint32_t)i * (16u * SP) + koff);
        uint32_t bfr[8][2];
        #pragma unroll
        for (int p = 0; p < 4; ++p) {
            uint32_t r[4];
            ldsm4(r, baddr + (uint32_t)p * (16u * SP) + koff);
            bfr[2*p][0]   = r[0]; bfr[2*p][1]   = r[1];
            bfr[2*p+1][0] = r[2]; bfr[2*p+1][1] = r[3];
        }
        #pragma unroll
        for (int i = 0; i < 4; ++i)
            #pragma unroll
            for (int j = 0; j < 8; ++j)
                mma16816(acc[i][j], afr[i], bfr[j]);
    }
}

__global__ __launch_bounds__(256, 1) void k_fused() {
    extern __shared__ char smem[];
    const int tid  = threadIdx.x;
    const int lane = tid & 31, wid = tid >> 5;
    const int b  = blockIdx.y;
    const int n0 = blockIdx.x * 128;
    const int cta = b * 32 + blockIdx.x;
    uint32_t sb = smem_to_u32(smem);
    const int wn0 = (wid & 1) * 64;
    const int wm0 = (wid >> 1) * 64;
    const int mg  = wid >> 1;            // m-group 0..3

    float* maxbuf = (float*)(smem + SM_RED);
    float* sumbuf = (float*)(smem + SM_RED + 2048);
    float* tvals  = (float*)(smem + SM_RED + 4096);
    float* cvals  = (float*)(smem + SM_RED + 4608);

    // ---- A tile (resident whole kernel) ----
    {
        int row = tid >> 1, off = (tid & 1) * 128;
        const uint4* gx = (const uint4*)((const char*)(g_X + ((size_t)b * N_ + n0 + row) * C_) + off);
        uint4* sx = (uint4*)(smem + row * SP + off);
        #pragma unroll
        for (int i = 0; i < 8; ++i) sx[i] = gx[i];
    }

    uint32_t aaddr = sb + (uint32_t)(wn0 + (lane & 15)) * SP + (uint32_t)(lane >> 4) * 16u;
    uint32_t boff  = (uint32_t)(wm0 + ((lane >> 4) & 1) * 8 + (lane & 7)) * SP
                   + (uint32_t)((lane >> 3) & 1) * 16u;

    // ================= pass 1: GEMM + row max + store S ====================
    float rmax[4][2];
    #pragma unroll
    for (int i = 0; i < 4; ++i) { rmax[i][0] = -1e30f; rmax[i][1] = -1e30f; }

    issue_B(b, 0, tid, sb);
    for (int ms = 0; ms < 16; ++ms) {
        asm volatile("cp.async.wait_group 0;" ::: "memory");
        __syncthreads();
        if (ms < 15) issue_B(b, ms + 1, tid, sb);
        float acc[4][8][4];
        compute_step(acc, aaddr, sb + SM_B + (uint32_t)(ms & 1) * BUF_B + boff);
        uint4* dst = g_Sf + (((size_t)cta * 16 + ms) * 16) * 256 + tid;
        #pragma unroll
        for (int g = 0; g < 16; ++g) {
            int i = g >> 2, j0 = (g & 3) * 2;
            rmax[i][0] = fmaxf(rmax[i][0],
                fmaxf(fmaxf(acc[i][j0][0], acc[i][j0][1]),
                      fmaxf(acc[i][j0+1][0], acc[i][j0+1][1])));
            rmax[i][1] = fmaxf(rmax[i][1],
                fmaxf(fmaxf(acc[i][j0][2], acc[i][j0][3]),
                      fmaxf(acc[i][j0+1][2], acc[i][j0+1][3])));
            __half2 a0 = __floats2half2_rn(acc[i][j0][0],   acc[i][j0][1]);
            __half2 b0 = __floats2half2_rn(acc[i][j0][2],   acc[i][j0][3]);
            __half2 a1 = __floats2half2_rn(acc[i][j0+1][0], acc[i][j0+1][1]);
            __half2 b1 = __floats2half2_rn(acc[i][j0+1][2], acc[i][j0+1][3]);
            uint4 v;
            v.x = *(uint32_t*)&a0; v.y = *(uint32_t*)&b0;
            v.z = *(uint32_t*)&a1; v.w = *(uint32_t*)&b1;
            dst[(size_t)g * 256] = v;
        }
    }
    #pragma unroll
    for (int i = 0; i < 4; ++i)
        #pragma unroll
        for (int z = 0; z < 2; ++z) {
            rmax[i][z] = fmaxf(rmax[i][z], __shfl_xor_sync(0xffffffffu, rmax[i][z], 1));
            rmax[i][z] = fmaxf(rmax[i][z], __shfl_xor_sync(0xffffffffu, rmax[i][z], 2));
        }
    if ((lane & 3) == 0) {
        #pragma unroll
        for (int i = 0; i < 4; ++i) {
            int r = wn0 + i * 16 + (lane >> 2);
            maxbuf[mg * 128 + r]     = rmax[i][0];
            maxbuf[mg * 128 + r + 8] = rmax[i][1];
        }
    }
    __syncthreads();
    if (tid < 128) {
        float m = fmaxf(fmaxf(maxbuf[tid], maxbuf[128 + tid]),
                        fmaxf(maxbuf[256 + tid], maxbuf[384 + tid]));
        float t = 10.0f / (1.001f - m);
        tvals[tid] = t;
        cvals[tid] = -m * t;
    }
    __syncthreads();

    float tA[4], cA[4], tB[4], cB[4];
    #pragma unroll
    for (int i = 0; i < 4; ++i) {
        int r = wn0 + i * 16 + (lane >> 2);
        tA[i] = tvals[r];     cA[i] = cvals[r];
        tB[i] = tvals[r + 8]; cB[i] = cvals[r + 8];
    }

    // ================= pass 2: stream S back + exp-sum =====================
    float rsum[4][2];
    #pragma unroll
    for (int i = 0; i < 4; ++i) { rsum[i][0] = 0.f; rsum[i][1] = 0.f; }

    for (int ms = 0; ms < 16; ++ms) {
        const uint4* src = g_Sf + (((size_t)cta * 16 + ms) * 16) * 256 + tid;
        uint4 v[16];
        #pragma unroll
        for (int g = 0; g < 16; ++g) v[g] = src[(size_t)g * 256];
        #pragma unroll
        for (int g = 0; g < 16; ++g) {
            int i = g >> 2;
            float2 a0 = __half22float2(*(__half2*)&v[g].x);
            float2 b0 = __half22float2(*(__half2*)&v[g].y);
            float2 a1 = __half22float2(*(__half2*)&v[g].z);
            float2 b1 = __half22float2(*(__half2*)&v[g].w);
            rsum[i][0] += (__expf(fmaf(a0.x, tA[i], cA[i]))
                         + __expf(fmaf(a0.y, tA[i], cA[i])))
                        + (__expf(fmaf(a1.x, tA[i], cA[i]))
                         + __expf(fmaf(a1.y, tA[i], cA[i])));
            rsum[i][1] += (__expf(fmaf(b0.x, tB[i], cB[i]))
                         + __expf(fmaf(b0.y, tB[i], cB[i])))
                        + (__expf(fmaf(b1.x, tB[i], cB[i]))
                         + __expf(fmaf(b1.y, tB[i], cB[i])));
        }
    }
    #pragma unroll
    for (int i = 0; i < 4; ++i)
        #pragma unroll
        for (int z = 0; z < 2; ++z) {
            rsum[i][z] += __shfl_xor_sync(0xffffffffu, rsum[i][z], 1);
            rsum[i][z] += __shfl_xor_sync(0xffffffffu, rsum[i][z], 2);
        }
    if ((lane & 3) == 0) {
        #pragma unroll
        for (int i = 0; i < 4; ++i) {
            int r = wn0 + i * 16 + (lane >> 2);
            sumbuf[mg * 128 + r]     = rsum[i][0];
            sumbuf[mg * 128 + r + 8] = rsum[i][1];
        }
    }
    __syncthreads();
    if (tid < 128) {
        float s = (sumbuf[tid] + sumbuf[128 + tid])
                + (sumbuf[256 + tid] + sumbuf[384 + tid]);
        g_A[b * N_ + n0 + tid] = 1.0f / s;
    }
}

// ---------------- kernel 5: final CX mean + -log ---------------------------
__global__ void k_final(float* __restrict__ out) {
    int b = blockIdx.x, tid = threadIdx.x;
    float s = 0.f;
    #pragma unroll
    for (int k = 0; k < N_ / 128; ++k) s += g_A[b * N_ + k * 128 + tid];
    __shared__ float sh[128];
    sh[tid] = s; __syncthreads();
    #pragma unroll
    for (int r = 64; r; r >>= 1) {
        if (tid < r) sh[tid] += sh[tid + r];
        __syncthreads();
    }
    if (tid == 0) out[b] = -logf(sh[0] * (1.0f / N_));
}

// ---------------- launcher -------------------------------------------------
extern "C" void kernel_launch(void* const* d_in, const int* in_sizes, int n_in,
                              void* d_out, int out_size) {
    const float* fx = (const float*)d_in[0];
    const float* fy = (const float*)d_in[1];
    float* out = (float*)d_out;

    cudaFuncSetAttribute(k_fused,
                         cudaFuncAttributeMaxDynamicSharedMemorySize, SM_FUS);

    k_mean_part<<<dim3(NG, B_), 128>>>(fy);
    k_mean_final<<<B_, 128>>>();
    k_normalize<<<(B_ * N_) / 8, 256>>>(fx, fy);
    k_fused<<<dim3(N_ / 128, B_), 256, SM_FUS>>>();
    k_final<<<B_, 128>>>(out);
}

// round 14
// speedup vs baseline: 1.0676x; 1.0676x over previous
#include <cuda_runtime.h>
#include <cuda_fp16.h>
#include <math.h>
#include <stdint.h>

#define B_  4
#define C_  128
#define N_  4096
#define NG  8

// ---------------- scratch (device globals; no allocs) ----------------------
__device__ float   g_part[B_ * NG * C_];
__device__ float   g_mean[B_ * C_];
__device__ __half  g_X[(size_t)B_ * N_ * C_];     // normalized fx, fp16 [b][n][c]
__device__ __half  g_Y[(size_t)B_ * N_ * C_];     // normalized fy, fp16 [b][n][c]
__device__ float   g_A[B_ * N_];                  // per-row 1/sum

// ---------------- warp MMA helpers (sm_80 PTX: works on compute_103) -------
__device__ __forceinline__ uint32_t smem_to_u32(const void* p) {
    uint32_t a;
    asm("{ .reg .u64 t; cvta.to.shared.u64 t, %1; cvt.u32.u64 %0, t; }"
        : "=r"(a) : "l"(p));
    return a;
}
__device__ __forceinline__ void ldsm4(uint32_t r[4], uint32_t addr) {
    asm volatile("ldmatrix.sync.aligned.m8n8.x4.shared.b16 {%0,%1,%2,%3}, [%4];"
                 : "=r"(r[0]), "=r"(r[1]), "=r"(r[2]), "=r"(r[3]) : "r"(addr));
}
__device__ __forceinline__ void mma16816(float c[4], const uint32_t a[4],
                                         const uint32_t b[2]) {
    asm volatile("mma.sync.aligned.m16n8k16.row.col.f32.f16.f16.f32 "
                 "{%0,%1,%2,%3}, {%4,%5,%6,%7}, {%8,%9}, {%0,%1,%2,%3};"
                 : "+f"(c[0]), "+f"(c[1]), "+f"(c[2]), "+f"(c[3])
                 : "r"(a[0]), "r"(a[1]), "r"(a[2]), "r"(a[3]),
                   "r"(b[0]), "r"(b[1]));
}

// ---------------- kernel 1a/1b: spatial mean of feature_y ------------------
__global__ void k_mean_part(const float* __restrict__ fy) {
    int b = blockIdx.y, g = blockIdx.x, c = threadIdx.x;
    const float* p = fy + ((size_t)b * N_ + (size_t)g * (N_ / NG)) * C_ + c;
    float s = 0.f;
    for (int n = 0; n < N_ / NG; ++n) s += p[(size_t)n * C_];
    g_part[(b * NG + g) * C_ + c] = s;
}
__global__ void k_mean_final() {
    int b = blockIdx.x, c = threadIdx.x;
    float s = 0.f;
    #pragma unroll
    for (int g = 0; g < NG; ++g) s += g_part[(b * NG + g) * C_ + c];
    g_mean[b * C_ + c] = s * (1.0f / N_);
}

// ---------------- kernel 2: center + L2-normalize -> fp16 ------------------
__global__ __launch_bounds__(256) void k_normalize(const float* __restrict__ fx,
                                                   const float* __restrict__ fy) {
    int w    = blockIdx.x * 8 + (threadIdx.x >> 5);
    int lane = threadIdx.x & 31;
    int b = w / N_, n = w % N_;
    size_t base = ((size_t)b * N_ + n) * C_ + lane * 4;
    float4 xv = *(const float4*)(fx + base);
    float4 yv = *(const float4*)(fy + base);
    float4 mv = *(const float4*)(g_mean + b * C_ + lane * 4);
    float cx[4] = {xv.x - mv.x, xv.y - mv.y, xv.z - mv.z, xv.w - mv.w};
    float cy[4] = {yv.x - mv.x, yv.y - mv.y, yv.z - mv.z, yv.w - mv.w};
    float ssx = cx[0]*cx[0] + cx[1]*cx[1] + cx[2]*cx[2] + cx[3]*cx[3];
    float ssy = cy[0]*cy[0] + cy[1]*cy[1] + cy[2]*cy[2] + cy[3]*cy[3];
    #pragma unroll
    for (int o = 16; o; o >>= 1) {
        ssx += __shfl_xor_sync(0xffffffffu, ssx, o);
        ssy += __shfl_xor_sync(0xffffffffu, ssy, o);
    }
    float sx = 1.0f / (sqrtf(ssx) + 1e-10f);
    float sy = 1.0f / (sqrtf(ssy) + 1e-10f);
    __half2 hx0 = __floats2half2_rn(cx[0]*sx, cx[1]*sx);
    __half2 hx1 = __floats2half2_rn(cx[2]*sx, cx[3]*sx);
    __half2 hy0 = __floats2half2_rn(cy[0]*sy, cy[1]*sy);
    __half2 hy1 = __floats2half2_rn(cy[2]*sy, cy[3]*sy);
    *(uint2*)(g_X + base) = make_uint2(*(uint32_t*)&hx0, *(uint32_t*)&hx1);
    *(uint2*)(g_Y + base) = make_uint2(*(uint32_t*)&hy0, *(uint32_t*)&hy1);
}

// ---------------- kernel 3: fused strip GEMM + row softmax -----------------
// CTA = 64 n-rows x all 4096 m. 128 threads, 4 warps side-by-side in m
// (warp tile 64n x 32m). A fragments preloaded into registers ONCE;
// per m-step only B ldsm. 32 steps of 64x128; two passes (max, exp-sum).
// SMEM ~89.6KB -> 2 CTAs/SM. Grid (64, 4) = 256 CTAs.
#define SP      272u                  // padded smem row stride (136 halves)
#define SM_A    0u
#define A_BYTES (64u * SP)            // 17408
#define SM_B    A_BYTES
#define BUF_B   (128u * SP)           // 34816
#define SM_RED  (SM_B + 2u * BUF_B)   // 87040
#define SM_FUS  (SM_RED + 2560u)      // maxbuf 1K + sumbuf 1K + t/c 512

__device__ __forceinline__ void issue_B(int b, int ms, int tid, uint32_t sb) {
    const char* src = (const char*)(g_Y + ((size_t)b * N_ + ms * 128) * C_);
    uint32_t dst = sb + SM_B + (uint32_t)(ms & 1) * BUF_B;
    #pragma unroll
    for (int k = 0; k < 16; ++k) {
        int cidx = tid + k * 128;
        int row = cidx >> 4, c16 = cidx & 15;
        uint32_t d = dst + (uint32_t)row * SP + (uint32_t)c16 * 16u;
        const char* s = src + (size_t)row * 256 + c16 * 16;
        asm volatile("cp.async.cg.shared.global [%0], [%1], 16;"
                     :: "r"(d), "l"(s) : "memory");
    }
    asm volatile("cp.async.commit_group;" ::: "memory");
}

// one 64x128 step: B ldsm only (A frags in registers)
__device__ __forceinline__ void compute_step(float acc[4][4][4],
                                             const uint32_t afr[8][4][4],
                                             uint32_t baddr) {
    #pragma unroll
    for (int i = 0; i < 4; ++i)
        #pragma unroll
        for (int j = 0; j < 4; ++j)
            #pragma unroll
            for (int k = 0; k < 4; ++k) acc[i][j][k] = 0.f;
    #pragma unroll
    for (int kc = 0; kc < 8; ++kc) {
        uint32_t koff = (uint32_t)kc * 32u;
        uint32_t bfr[4][2];
        #pragma unroll
        for (int p = 0; p < 2; ++p) {
            uint32_t r[4];
            ldsm4(r, baddr + (uint32_t)p * (16u * SP) + koff);
            bfr[2*p][0]   = r[0]; bfr[2*p][1]   = r[1];
            bfr[2*p+1][0] = r[2]; bfr[2*p+1][1] = r[3];
        }
        #pragma unroll
        for (int i = 0; i < 4; ++i)
            #pragma unroll
            for (int j = 0; j < 4; ++j)
                mma16816(acc[i][j], afr[kc][i], bfr[j]);
    }
}

__global__ __launch_bounds__(128, 2) void k_fused() {
    extern __shared__ char smem[];
    const int tid  = threadIdx.x;
    const int lane = tid & 31, wid = tid >> 5;
    const int b  = blockIdx.y;
    const int n0 = blockIdx.x * 64;
    uint32_t sb = smem_to_u32(smem);
    const int wm0 = wid * 32;            // warp m offset within 128-step

    float* maxbuf = (float*)(smem + SM_RED);           // [4][64]
    float* sumbuf = (float*)(smem + SM_RED + 1024);    // [4][64]
    float* tvals  = (float*)(smem + SM_RED + 2048);    // [64]
    float* cvals  = (float*)(smem + SM_RED + 2304);    // [64]

    // ---- A tile to SMEM (64 rows) ----
    {
        int row = tid >> 1, off = (tid & 1) * 128;
        const uint4* gx = (const uint4*)((const char*)(g_X + ((size_t)b * N_ + n0 + row) * C_) + off);
        uint4* sx = (uint4*)(smem + row * SP + off);
        #pragma unroll
        for (int i = 0; i < 8; ++i) sx[i] = gx[i];
    }
    __syncthreads();

    // ---- preload ALL A fragments into registers (once per kernel) ----
    uint32_t afr[8][4][4];
    {
        uint32_t aaddr = sb + (uint32_t)(lane & 15) * SP + (uint32_t)(lane >> 4) * 16u;
        #pragma unroll
        for (int kc = 0; kc < 8; ++kc)
            #pragma unroll
            for (int i = 0; i < 4; ++i)
                ldsm4(afr[kc][i], aaddr + (uint32_t)i * (16u * SP) + (uint32_t)kc * 32u);
    }

    uint32_t boff = (uint32_t)(wm0 + ((lane >> 4) & 1) * 8 + (lane & 7)) * SP
                  + (uint32_t)((lane >> 3) & 1) * 16u;

    // ================= pass 1: per-row max =================
    float rmax[4][2];
    #pragma unroll
    for (int i = 0; i < 4; ++i) { rmax[i][0] = -1e30f; rmax[i][1] = -1e30f; }

    issue_B(b, 0, tid, sb);
    for (int ms = 0; ms < 32; ++ms) {
        asm volatile("cp.async.wait_group 0;" ::: "memory");
        __syncthreads();
        if (ms < 31) issue_B(b, ms + 1, tid, sb);
        float acc[4][4][4];
        compute_step(acc, afr, sb + SM_B + (uint32_t)(ms & 1) * BUF_B + boff);
        #pragma unroll
        for (int i = 0; i < 4; ++i)
            #pragma unroll
            for (int j = 0; j < 4; ++j) {
                rmax[i][0] = fmaxf(rmax[i][0], fmaxf(acc[i][j][0], acc[i][j][1]));
                rmax[i][1] = fmaxf(rmax[i][1], fmaxf(acc[i][j][2], acc[i][j][3]));
            }
    }
    #pragma unroll
    for (int i = 0; i < 4; ++i)
        #pragma unroll
        for (int z = 0; z < 2; ++z) {
            rmax[i][z] = fmaxf(rmax[i][z], __shfl_xor_sync(0xffffffffu, rmax[i][z], 1));
            rmax[i][z] = fmaxf(rmax[i][z], __shfl_xor_sync(0xffffffffu, rmax[i][z], 2));
        }
    if ((lane & 3) == 0) {
        #pragma unroll
        for (int i = 0; i < 4; ++i) {
            int r = i * 16 + (lane >> 2);
            maxbuf[wid * 64 + r]     = rmax[i][0];
            maxbuf[wid * 64 + r + 8] = rmax[i][1];
        }
    }
    __syncthreads();
    if (tid < 64) {
        float m = fmaxf(fmaxf(maxbuf[tid], maxbuf[64 + tid]),
                        fmaxf(maxbuf[128 + tid], maxbuf[192 + tid]));
        float t = 10.0f / (1.001f - m);
        tvals[tid] = t;
        cvals[tid] = -m * t;
    }
    __syncthreads();

    float tA[4], cA[4], tB[4], cB[4];
    #pragma unroll
    for (int i = 0; i < 4; ++i) {
        int r = i * 16 + (lane >> 2);
        tA[i] = tvals[r];     cA[i] = cvals[r];
        tB[i] = tvals[r + 8]; cB[i] = cvals[r + 8];
    }

    // ================= pass 2: exp-sum (bit-identical recompute) ===========
    float rsum[4][2];
    #pragma unroll
    for (int i = 0; i < 4; ++i) { rsum[i][0] = 0.f; rsum[i][1] = 0.f; }

    issue_B(b, 0, tid, sb);
    for (int ms = 0; ms < 32; ++ms) {
        asm volatile("cp.async.wait_group 0;" ::: "memory");
        __syncthreads();
        if (ms < 31) issue_B(b, ms + 1, tid, sb);
        float acc[4][4][4];
        compute_step(acc, afr, sb + SM_B + (uint32_t)(ms & 1) * BUF_B + boff);
        #pragma unroll
        for (int i = 0; i < 4; ++i)
            #pragma unroll
            for (int j = 0; j < 4; ++j) {
                rsum[i][0] += __expf(fmaf(acc[i][j][0], tA[i], cA[i]))
                            + __expf(fmaf(acc[i][j][1], tA[i], cA[i]));
                rsum[i][1] += __expf(fmaf(acc[i][j][2], tB[i], cB[i]))
                            + __expf(fmaf(acc[i][j][3], tB[i], cB[i]));
            }
    }
    #pragma unroll
    for (int i = 0; i < 4; ++i)
        #pragma unroll
        for (int z = 0; z < 2; ++z) {
            rsum[i][z] += __shfl_xor_sync(0xffffffffu, rsum[i][z], 1);
            rsum[i][z] += __shfl_xor_sync(0xffffffffu, rsum[i][z], 2);
        }
    if ((lane & 3) == 0) {
        #pragma unroll
        for (int i = 0; i < 4; ++i) {
            int r = i * 16 + (lane >> 2);
            sumbuf[wid * 64 + r]     = rsum[i][0];
            sumbuf[wid * 64 + r + 8] = rsum[i][1];
        }
    }
    __syncthreads();
    if (tid < 64) {
        float s = (sumbuf[tid] + sumbuf[64 + tid])
                + (sumbuf[128 + tid] + sumbuf[192 + tid]);
        g_A[b * N_ + n0 + tid] = 1.0f / s;
    }
}

// ---------------- kernel 5: final CX mean + -log ---------------------------
__global__ void k_final(float* __restrict__ out) {
    int b = blockIdx.x, tid = threadIdx.x;
    float s = 0.f;
    #pragma unroll
    for (int k = 0; k < N_ / 128; ++k) s += g_A[b * N_ + k * 128 + tid];
    __shared__ float sh[128];
    sh[tid] = s; __syncthreads();
    #pragma unroll
    for (int r = 64; r; r >>= 1) {
        if (tid < r) sh[tid] += sh[tid + r];
        __syncthreads();
    }
    if (tid == 0) out[b] = -logf(sh[0] * (1.0f / N_));
}

// ---------------- launcher -------------------------------------------------
extern "C" void kernel_launch(void* const* d_in, const int* in_sizes, int n_in,
                              void* d_out, int out_size) {
    const float* fx = (const float*)d_in[0];
    const float* fy = (const float*)d_in[1];
    float* out = (float*)d_out;

    cudaFuncSetAttribute(k_fused,
                         cudaFuncAttributeMaxDynamicSharedMemorySize, SM_FUS);

    k_mean_part<<<dim3(NG, B_), 128>>>(fy);
    k_mean_final<<<B_, 128>>>();
    k_normalize<<<(B_ * N_) / 8, 256>>>(fx, fy);
    k_fused<<<dim3(N_ / 64, B_), 128, SM_FUS>>>();
    k_final<<<B_, 128>>>(out);
}

// round 16
// speedup vs baseline: 1.2149x; 1.1380x over previous
#include <cuda_runtime.h>
#include <cuda_fp16.h>
#include <math.h>
#include <stdint.h>

#define B_  4
#define C_  128
#define N_  4096
#define NG  8

// ---------------- scratch (device globals; no allocs) ----------------------
__device__ float   g_part[B_ * NG * C_];
__device__ float   g_mean[B_ * C_];
__device__ __half  g_X[(size_t)B_ * N_ * C_];     // normalized fx, fp16 [b][n][c]
__device__ __half  g_Y[(size_t)B_ * N_ * C_];     // normalized fy, fp16 [b][n][c]
__device__ float   g_A[B_ * N_];                  // per-row 1/sum

// ---------------- warp MMA helpers (sm_80 PTX: works on compute_103) -------
__device__ __forceinline__ uint32_t smem_to_u32(const void* p) {
    uint32_t a;
    asm("{ .reg .u64 t; cvta.to.shared.u64 t, %1; cvt.u32.u64 %0, t; }"
        : "=r"(a) : "l"(p));
    return a;
}
__device__ __forceinline__ void ldsm4(uint32_t r[4], uint32_t addr) {
    asm volatile("ldmatrix.sync.aligned.m8n8.x4.shared.b16 {%0,%1,%2,%3}, [%4];"
                 : "=r"(r[0]), "=r"(r[1]), "=r"(r[2]), "=r"(r[3]) : "r"(addr));
}
__device__ __forceinline__ void mma16816(float c[4], const uint32_t a[4],
                                         const uint32_t b[2]) {
    asm volatile("mma.sync.aligned.m16n8k16.row.col.f32.f16.f16.f32 "
                 "{%0,%1,%2,%3}, {%4,%5,%6,%7}, {%8,%9}, {%0,%1,%2,%3};"
                 : "+f"(c[0]), "+f"(c[1]), "+f"(c[2]), "+f"(c[3])
                 : "r"(a[0]), "r"(a[1]), "r"(a[2]), "r"(a[3]),
                   "r"(b[0]), "r"(b[1]));
}

// ---------------- kernel 1a/1b: spatial mean of feature_y ------------------
__global__ void k_mean_part(const float* __restrict__ fy) {
    int b = blockIdx.y, g = blockIdx.x, c = threadIdx.x;
    const float* p = fy + ((size_t)b * N_ + (size_t)g * (N_ / NG)) * C_ + c;
    float s = 0.f;
    for (int n = 0; n < N_ / NG; ++n) s += p[(size_t)n * C_];
    g_part[(b * NG + g) * C_ + c] = s;
}
__global__ void k_mean_final() {
    int b = blockIdx.x, c = threadIdx.x;
    float s = 0.f;
    #pragma unroll
    for (int g = 0; g < NG; ++g) s += g_part[(b * NG + g) * C_ + c];
    g_mean[b * C_ + c] = s * (1.0f / N_);
}

// ---------------- kernel 2: center + L2-normalize -> fp16 ------------------
__global__ __launch_bounds__(256) void k_normalize(const float* __restrict__ fx,
                                                   const float* __restrict__ fy) {
    int w    = blockIdx.x * 8 + (threadIdx.x >> 5);
    int lane = threadIdx.x & 31;
    int b = w / N_, n = w % N_;
    size_t base = ((size_t)b * N_ + n) * C_ + lane * 4;
    float4 xv = *(const float4*)(fx + base);
    float4 yv = *(const float4*)(fy + base);
    float4 mv = *(const float4*)(g_mean + b * C_ + lane * 4);
    float cx[4] = {xv.x - mv.x, xv.y - mv.y, xv.z - mv.z, xv.w - mv.w};
    float cy[4] = {yv.x - mv.x, yv.y - mv.y, yv.z - mv.z, yv.w - mv.w};
    float ssx = cx[0]*cx[0] + cx[1]*cx[1] + cx[2]*cx[2] + cx[3]*cx[3];
    float ssy = cy[0]*cy[0] + cy[1]*cy[1] + cy[2]*cy[2] + cy[3]*cy[3];
    #pragma unroll
    for (int o = 16; o; o >>= 1) {
        ssx += __shfl_xor_sync(0xffffffffu, ssx, o);
        ssy += __shfl_xor_sync(0xffffffffu, ssy, o);
    }
    float sx = 1.0f / (sqrtf(ssx) + 1e-10f);
    float sy = 1.0f / (sqrtf(ssy) + 1e-10f);
    __half2 hx0 = __floats2half2_rn(cx[0]*sx, cx[1]*sx);
    __half2 hx1 = __floats2half2_rn(cx[2]*sx, cx[3]*sx);
    __half2 hy0 = __floats2half2_rn(cy[0]*sy, cy[1]*sy);
    __half2 hy1 = __floats2half2_rn(cy[2]*sy, cy[3]*sy);
    *(uint2*)(g_X + base) = make_uint2(*(uint32_t*)&hx0, *(uint32_t*)&hx1);
    *(uint2*)(g_Y + base) = make_uint2(*(uint32_t*)&hy0, *(uint32_t*)&hy1);
}

// ---------------- kernel 3: fused strip GEMM + row softmax -----------------
// CTA = 64 n-rows x all 4096 m, 128 threads. Each warp owns a PRIVATE
// 1024-col m-slice with its own double-buffered SMEM B region and its own
// cp.async pipeline -> ZERO __syncthreads in the hot loops. A fragments in
// registers (loaded once). 32 steps of 64n x 32m per warp; two passes.
#define SP      272u                  // padded smem row stride (136 halves)
#define A_BYTES (64u * SP)            // 17408
#define SM_B    A_BYTES
#define WBUF    (32u * SP)            // 8704 per buffer
#define WREG    (2u * WBUF)           // 17408 per warp (double buffer)
#define SM_RED  (SM_B + 4u * WREG)    // 87040
#define SM_FUS  (SM_RED + 2560u)      // maxbuf 1K + sumbuf 1K + t/c 512

// per-warp B slice load: 32 rows x 256B from g_Y, warp-private buffer
__device__ __forceinline__ void issue_Bw(int b, int wid, int ms, int lane,
                                         uint32_t sb) {
    const char* src = (const char*)(g_Y + ((size_t)b * N_ + wid * 1024 + ms * 32) * C_);
    uint32_t dst = sb + SM_B + (uint32_t)wid * WREG + (uint32_t)(ms & 1) * WBUF;
    #pragma unroll
    for (int k = 0; k < 16; ++k) {
        int idx = lane + k * 32;
        int row = idx >> 4, c16 = idx & 15;
        uint32_t d = dst + (uint32_t)row * SP + (uint32_t)c16 * 16u;
        const char* s = src + (size_t)row * 256 + c16 * 16;
        asm volatile("cp.async.cg.shared.global [%0], [%1], 16;"
                     :: "r"(d), "l"(s) : "memory");
    }
    asm volatile("cp.async.commit_group;" ::: "memory");
}

// one 64x32 warp step: B ldsm only (A frags in registers)
__device__ __forceinline__ void compute_step(float acc[4][4][4],
                                             const uint32_t afr[8][4][4],
                                             uint32_t baddr) {
    #pragma unroll
    for (int i = 0; i < 4; ++i)
        #pragma unroll
        for (int j = 0; j < 4; ++j)
            #pragma unroll
            for (int k = 0; k < 4; ++k) acc[i][j][k] = 0.f;
    #pragma unroll
    for (int kc = 0; kc < 8; ++kc) {
        uint32_t koff = (uint32_t)kc * 32u;
        uint32_t bfr[4][2];
        #pragma unroll
        for (int p = 0; p < 2; ++p) {
            uint32_t r[4];
            ldsm4(r, baddr + (uint32_t)p * (16u * SP) + koff);
            bfr[2*p][0]   = r[0]; bfr[2*p][1]   = r[1];
            bfr[2*p+1][0] = r[2]; bfr[2*p+1][1] = r[3];
        }
        #pragma unroll
        for (int i = 0; i < 4; ++i)
            #pragma unroll
            for (int j = 0; j < 4; ++j)
                mma16816(acc[i][j], afr[kc][i], bfr[j]);
    }
}

__global__ __launch_bounds__(128, 2) void k_fused() {
    extern __shared__ char smem[];
    const int tid  = threadIdx.x;
    const int lane = tid & 31, wid = tid >> 5;
    const int b  = blockIdx.y;
    const int n0 = blockIdx.x * 64;
    uint32_t sb = smem_to_u32(smem);

    float* maxbuf = (float*)(smem + SM_RED);           // [4][64]
    float* sumbuf = (float*)(smem + SM_RED + 1024);    // [4][64]
    float* tvals  = (float*)(smem + SM_RED + 2048);    // [64]
    float* cvals  = (float*)(smem + SM_RED + 2304);    // [64]

    // ---- A tile to SMEM (64 rows), then all warps preload identical frags -
    {
        int row = tid >> 1, off = (tid & 1) * 128;
        const uint4* gx = (const uint4*)((const char*)(g_X + ((size_t)b * N_ + n0 + row) * C_) + off);
        uint4* sx = (uint4*)(smem + row * SP + off);
        #pragma unroll
        for (int i = 0; i < 8; ++i) sx[i] = gx[i];
    }
    __syncthreads();

    uint32_t afr[8][4][4];
    {
        uint32_t aaddr = sb + (uint32_t)(lane & 15) * SP + (uint32_t)(lane >> 4) * 16u;
        #pragma unroll
        for (int kc = 0; kc < 8; ++kc)
            #pragma unroll
            for (int i = 0; i < 4; ++i)
                ldsm4(afr[kc][i], aaddr + (uint32_t)i * (16u * SP) + (uint32_t)kc * 32u);
    }

    // warp-private B base + ldsm offset (m-local within 32-col step tile)
    const uint32_t wbase = sb + SM_B + (uint32_t)wid * WREG;
    const uint32_t boff  = (uint32_t)(((lane >> 4) & 1) * 8 + (lane & 7)) * SP
                         + (uint32_t)((lane >> 3) & 1) * 16u;

    // ================= pass 1: per-row max (no CTA barriers) ===============
    float rmax[4][2];
    #pragma unroll
    for (int i = 0; i < 4; ++i) { rmax[i][0] = -1e30f; rmax[i][1] = -1e30f; }

    issue_Bw(b, wid, 0, lane, sb);
    for (int ms = 0; ms < 32; ++ms) {
        asm volatile("cp.async.wait_group 0;" ::: "memory");
        __syncwarp();
        if (ms < 31) issue_Bw(b, wid, ms + 1, lane, sb);
        float acc[4][4][4];
        compute_step(acc, afr, wbase + (uint32_t)(ms & 1) * WBUF + boff);
        #pragma unroll
        for (int i = 0; i < 4; ++i)
            #pragma unroll
            for (int j = 0; j < 4; ++j) {
                rmax[i][0] = fmaxf(rmax[i][0], fmaxf(acc[i][j][0], acc[i][j][1]));
                rmax[i][1] = fmaxf(rmax[i][1], fmaxf(acc[i][j][2], acc[i][j][3]));
            }
    }
    #pragma unroll
    for (int i = 0; i < 4; ++i)
        #pragma unroll
        for (int z = 0; z < 2; ++z) {
            rmax[i][z] = fmaxf(rmax[i][z], __shfl_xor_sync(0xffffffffu, rmax[i][z], 1));
            rmax[i][z] = fmaxf(rmax[i][z], __shfl_xor_sync(0xffffffffu, rmax[i][z], 2));
        }
    if ((lane & 3) == 0) {
        #pragma unroll
        for (int i = 0; i < 4; ++i) {
            int r = i * 16 + (lane >> 2);
            maxbuf[wid * 64 + r]     = rmax[i][0];
            maxbuf[wid * 64 + r + 8] = rmax[i][1];
        }
    }
    __syncthreads();
    if (tid < 64) {
        float m = fmaxf(fmaxf(maxbuf[tid], maxbuf[64 + tid]),
                        fmaxf(maxbuf[128 + tid], maxbuf[192 + tid]));
        float t = 10.0f / (1.001f - m);
        tvals[tid] = t;
        cvals[tid] = -m * t;
    }
    __syncthreads();

    float tA[4], cA[4], tB[4], cB[4];
    #pragma unroll
    for (int i = 0; i < 4; ++i) {
        int r = i * 16 + (lane >> 2);
        tA[i] = tvals[r];     cA[i] = cvals[r];
        tB[i] = tvals[r + 8]; cB[i] = cvals[r + 8];
    }

    // ================= pass 2: exp-sum (bit-identical recompute) ===========
    float rsum[4][2];
    #pragma unroll
    for (int i = 0; i < 4; ++i) { rsum[i][0] = 0.f; rsum[i][1] = 0.f; }

    issue_Bw(b, wid, 0, lane, sb);
    for (int ms = 0; ms < 32; ++ms) {
        asm volatile("cp.async.wait_group 0;" ::: "memory");
        __syncwarp();
        if (ms < 31) issue_Bw(b, wid, ms + 1, lane, sb);
        float acc[4][4][4];
        compute_step(acc, afr, wbase + (uint32_t)(ms & 1) * WBUF + boff);
        #pragma unroll
        for (int i = 0; i < 4; ++i)
            #pragma unroll
            for (int j = 0; j < 4; ++j) {
                rsum[i][0] += __expf(fmaf(acc[i][j][0], tA[i], cA[i]))
                            + __expf(fmaf(acc[i][j][1], tA[i], cA[i]));
                rsum[i][1] += __expf(fmaf(acc[i][j][2], tB[i], cB[i]))
                            + __expf(fmaf(acc[i][j][3], tB[i], cB[i]));
            }
    }
    #pragma unroll
    for (int i = 0; i < 4; ++i)
        #pragma unroll
        for (int z = 0; z < 2; ++z) {
            rsum[i][z] += __shfl_xor_sync(0xffffffffu, rsum[i][z], 1);
            rsum[i][z] += __shfl_xor_sync(0xffffffffu, rsum[i][z], 2);
        }
    if ((lane & 3) == 0) {
        #pragma unroll
        for (int i = 0; i < 4; ++i) {
            int r = i * 16 + (lane >> 2);
            sumbuf[wid * 64 + r]     = rsum[i][0];
            sumbuf[wid * 64 + r + 8] = rsum[i][1];
        }
    }
    __syncthreads();
    if (tid < 64) {
        float s = (sumbuf[tid] + sumbuf[64 + tid])
                + (sumbuf[128 + tid] + sumbuf[192 + tid]);
        g_A[b * N_ + n0 + tid] = 1.0f / s;
    }
}

// ---------------- kernel 5: final CX mean + -log ---------------------------
__global__ void k_final(float* __restrict__ out) {
    int b = blockIdx.x, tid = threadIdx.x;
    float s = 0.f;
    #pragma unroll
    for (int k = 0; k < N_ / 128; ++k) s += g_A[b * N_ + k * 128 + tid];
    __shared__ float sh[128];
    sh[tid] = s; __syncthreads();
    #pragma unroll
    for (int r = 64; r; r >>= 1) {
        if (tid < r) sh[tid] += sh[tid + r];
        __syncthreads();
    }
    if (tid == 0) out[b] = -logf(sh[0] * (1.0f / N_));
}

// ---------------- launcher -------------------------------------------------
extern "C" void kernel_launch(void* const* d_in, const int* in_sizes, int n_in,
                              void* d_out, int out_size) {
    const float* fx = (const float*)d_in[0];
    const float* fy = (const float*)d_in[1];
    float* out = (float*)d_out;

    cudaFuncSetAttribute(k_fused,
                         cudaFuncAttributeMaxDynamicSharedMemorySize, SM_FUS);

    k_mean_part<<<dim3(NG, B_), 128>>>(fy);
    k_mean_final<<<B_, 128>>>();
    k_normalize<<<(B_ * N_) / 8, 256>>>(fx, fy);
    k_fused<<<dim3(N_ / 64, B_), 128, SM_FUS>>>();
    k_final<<<B_, 128>>>(out);
}